// round 13
// baseline (speedup 1.0000x reference)
#include <cuda_runtime.h>
#include <cuda_bf16.h>
#include <math.h>

#define B_SZ 32768
#define K_SZ 64
#define D_SZ 64

#define CHUNKS 4
#define KPC 16            // k per chunk
#define BPC 37            // blocks per chunk
#define GRID_MAIN 148     // CHUNKS * BPC = 1 wave exactly
#define THREADS_MAIN 256  // 8 warps x 16 samples
#define TILE_S 128
#define NTILES 256        // B_SZ / TILE_S

#define S_MEAN  (1.0f / 64.0f)
#define S_SCALE (1.0f / 512.0f)
#define S_W     (0.125f)
#define LOG_2PI 1.8378770664093453f
#define NEG_BIG (-3.0e38f)

// dynamic smem: E chunk 128KB | m2 4KB | c 64B  (+1KB align slack)
#define SM_M2   131072
#define SM_C    135168
#define SMEM_BYTES 137728

__device__ __nv_bfloat16 g_Eb[K_SZ * D_SZ * D_SZ];   // E = Linv - I (bf16)
__device__ float g_m2[K_SZ * D_SZ];
__device__ float g_c[K_SZ];
__device__ float g_logw[K_SZ];
__device__ float g_pm[CHUNKS * B_SZ];
__device__ float g_ps[CHUNKS * B_SZ];
__device__ float g_partial[128];

// ---------------- PTX helpers (braces in strings written as \173 \175) ----
__device__ __forceinline__ void cp16(unsigned dst, const void* src) {
    asm volatile("cp.async.cg.shared.global [%0], [%1], 16;"
                 :: "r"(dst), "l"(__cvta_generic_to_global(src)) : "memory");
}
__device__ __forceinline__ void cp_commit() {
    asm volatile("cp.async.commit_group;" ::: "memory");
}
__device__ __forceinline__ void cp_wait0() {
    asm volatile("cp.async.wait_group 0;" ::: "memory");
}
__device__ __forceinline__ void ldsm4(unsigned& r0, unsigned& r1,
                                      unsigned& r2, unsigned& r3, unsigned a) {
    asm volatile("ldmatrix.sync.aligned.m8n8.x4.shared.b16 \173%0,%1,%2,%3\175, [%4];"
                 : "=r"(r0), "=r"(r1), "=r"(r2), "=r"(r3) : "r"(a));
}
__device__ __forceinline__ void mma_bf16(float& c0, float& c1, float& c2, float& c3,
                                         unsigned a0, unsigned a1, unsigned a2, unsigned a3,
                                         unsigned b0, unsigned b1) {
    asm volatile("mma.sync.aligned.m16n8k16.row.col.f32.bf16.bf16.f32 "
                 "\173%0,%1,%2,%3\175, \173%4,%5,%6,%7\175, \173%8,%9\175, \173%0,%1,%2,%3\175;"
                 : "+f"(c0), "+f"(c1), "+f"(c2), "+f"(c3)
                 : "r"(a0), "r"(a1), "r"(a2), "r"(a3), "r"(b0), "r"(b1));
}
__device__ __forceinline__ unsigned pack_bf16x2(float lo, float hi) {
    __nv_bfloat162 h = __floats2bfloat162_rn(lo, hi);
    return *reinterpret_cast<unsigned*>(&h);
}
__device__ __forceinline__ float2 unpack_bf16x2(unsigned u) {
    __nv_bfloat162 h = *reinterpret_cast<__nv_bfloat162*>(&u);
    return __bfloat1622float2(h);
}

// ---------------------------------------------------------------------------
__global__ void logw_kernel(const float* __restrict__ wraw) {
    __shared__ float red[K_SZ];
    int t = threadIdx.x;
    float v = wraw[t] * S_W;
    red[t] = v;
    __syncthreads();
    for (int s = 32; s > 0; s >>= 1) {
        if (t < s) red[t] = fmaxf(red[t], red[t + s]);
        __syncthreads();
    }
    float m = red[0];
    __syncthreads();
    red[t] = __expf(v - m);
    __syncthreads();
    for (int s = 32; s > 0; s >>= 1) {
        if (t < s) red[t] += red[t + s];
        __syncthreads();
    }
    float lse = m + __logf(red[0]);
    g_logw[t] = v - lse;
}

__global__ void prep_kernel(const float* __restrict__ means_raw,
                            const float* __restrict__ scale_raw) {
    __shared__ float sL [D_SZ * D_SZ];
    __shared__ float sLI[D_SZ * D_SZ];
    __shared__ float red[D_SZ];
    int k = blockIdx.x;
    int t = threadIdx.x;
    const float* src = scale_raw + (size_t)k * D_SZ * D_SZ;

    for (int idx = t; idx < D_SZ * D_SZ; idx += D_SZ) {
        int i = idx >> 6;
        int j = idx & 63;
        float v = src[idx] * S_SCALE;
        float dv = expf(v);
        float off = (j < i) ? v : 0.0f;
        sL[idx] = (j == i) ? dv : off;
    }
    red[t] = src[t * D_SZ + t] * S_SCALE;
    __syncthreads();
    for (int s = 32; s > 0; s >>= 1) {
        if (t < s) red[t] += red[t + s];
        __syncthreads();
    }
    float hld = red[0];

    int j = t;
    for (int i = 0; i < j; ++i) sLI[i * D_SZ + j] = 0.0f;
    sLI[j * D_SZ + j] = 1.0f / sL[j * D_SZ + j];
    for (int i = j + 1; i < D_SZ; ++i) {
        float s = 0.0f;
        for (int m = j; m < i; ++m)
            s += sL[i * D_SZ + m] * sLI[m * D_SZ + j];
        sLI[i * D_SZ + j] = -s / sL[i * D_SZ + i];
    }
    __syncthreads();

    float mm = 0.0f;
    for (int jj = 0; jj <= t; ++jj)
        mm += sLI[t * D_SZ + jj] * (means_raw[k * D_SZ + jj] * S_MEAN);
    g_m2[k * D_SZ + t] = mm;

    if (t == 0)
        g_c[k] = -0.5f * (float)D_SZ * LOG_2PI - hld + g_logw[k];

    // store E = Linv - I (bf16): systematic rounding error scales with |E|,
    // not |Linv| -- the unit diagonal is re-added exactly in fp32 downstream
    for (int idx = t; idx < D_SZ * D_SZ; idx += D_SZ) {
        int i = idx >> 6;
        int jj2 = idx & 63;
        float v = sLI[idx] - ((i == jj2) ? 1.0f : 0.0f);
        g_Eb[(size_t)k * 4096 + idx] = __float2bfloat16(v);
    }
}

// ---------------------------------------------------------------------------
// Main: split-k persistent. Block = one k-chunk (16 k), E chunk resident in
// smem (XOR-swizzled) for the whole kernel. z = x + E*x - m2 (identity in
// fp32 from A-frags). 4 independent MMA chains per nt.
// ---------------------------------------------------------------------------
extern __shared__ __align__(16) char dsm[];

__global__ void __launch_bounds__(THREADS_MAIN)
main_kernel(const float* __restrict__ x) {
    const int tid  = threadIdx.x;
    const int warp = tid >> 5;
    const int lane = tid & 31;
    const int g    = lane >> 2;
    const int qt   = lane & 3;

    unsigned raw = (unsigned)__cvta_generic_to_shared(dsm);
    unsigned ab = (raw + 1023u) & ~1023u;
    char* abp = dsm + (ab - raw);

    const unsigned wa  = ab;
    const unsigned m2a = ab + SM_M2;
    const unsigned ca  = ab + SM_C;
    const float* sm2 = (const float*)(abp + SM_M2);
    const float* sc  = (const float*)(abp + SM_C);

    const int chunk = blockIdx.x & 3;
    const int jb    = blockIdx.x >> 2;     // 0..36
    const int k0    = chunk * KPC;

    // ---- stage E chunk (16k x 8KB, swizzled) + m2 + c, once ----
    for (int c = tid; c < KPC * 512; c += THREADS_MAIN) {
        int k   = c >> 9;
        int rem = c & 511;
        int row = rem >> 3;
        int cc  = rem & 7;
        unsigned dst = wa + (unsigned)(k * 8192 + row * 128 + ((cc ^ (row & 7)) * 16));
        cp16(dst, g_Eb + (size_t)(k0 + k) * 4096 + row * 64 + cc * 8);
    }
    {
        int c = tid;
        if (c < 256) cp16(m2a + (unsigned)(c * 16), g_m2 + k0 * 64 + c * 4);
        if (c < 4)   cp16(ca + (unsigned)(c * 16), g_c + k0 + c * 4);
    }
    cp_commit();
    cp_wait0();
    __syncthreads();

    const unsigned rbase = (unsigned)((lane & 7) * 128);
    const unsigned c0off = (unsigned)((((lane >> 3)) ^ (lane & 7)) * 16);
    const unsigned c1off = (unsigned)((((lane >> 3) + 4) ^ (lane & 7)) * 16);

    for (int t = jb; t < NTILES; t += BPC) {
        const int mb = t * TILE_S + warp * 16;
        const float* xr0 = x + (size_t)(mb + g) * D_SZ;
        const float* xr1 = x + (size_t)(mb + g + 8) * D_SZ;

        unsigned A[16];
#pragma unroll
        for (int jt = 0; jt < 4; ++jt) {
#pragma unroll
            for (int part = 0; part < 4; ++part) {
                const float* rp = (part & 1) ? xr1 : xr0;
                int jj = jt * 16 + 2 * qt + ((part & 2) ? 8 : 0);
                float2 v = *(const float2*)(rp + jj);
                A[jt * 4 + part] = pack_bf16x2(v.x, v.y);
            }
        }

        float mx0 = NEG_BIG, s0 = 0.0f;
        float mx1 = NEG_BIG, s1 = 0.0f;

        for (int kk = 0; kk < KPC; ++kk) {
            const unsigned wk = wa + (unsigned)(kk * 8192) + rbase;
            const float* m2k = sm2 + kk * 64;

            float mh0 = 0.0f, mh1 = 0.0f;
#pragma unroll
            for (int nt = 0; nt < 8; ++nt) {
                unsigned base = wk + (unsigned)(nt * 1024);
                unsigned bh0, bh1, bh2, bh3, bg0, bg1, bg2, bg3;
                ldsm4(bh0, bh1, bh2, bh3, base + c0off);
                ldsm4(bg0, bg1, bg2, bg3, base + c1off);

                // 4 independent depth-1 MMA chains
                float da0 = 0.0f, da1 = 0.0f, da2 = 0.0f, da3 = 0.0f;
                float db0 = 0.0f, db1 = 0.0f, db2 = 0.0f, db3 = 0.0f;
                float dc0 = 0.0f, dc1 = 0.0f, dc2 = 0.0f, dc3 = 0.0f;
                float dd0 = 0.0f, dd1 = 0.0f, dd2 = 0.0f, dd3 = 0.0f;
                mma_bf16(da0, da1, da2, da3, A[0],  A[1],  A[2],  A[3],  bh0, bh1);
                mma_bf16(db0, db1, db2, db3, A[4],  A[5],  A[6],  A[7],  bh2, bh3);
                mma_bf16(dc0, dc1, dc2, dc3, A[8],  A[9],  A[10], A[11], bg0, bg1);
                mma_bf16(dd0, dd1, dd2, dd3, A[12], A[13], A[14], A[15], bg2, bg3);

                // identity term: x values for output cols nt*8+2qt(+1),
                // rows g / g+8 -- exactly the A-frag contents
                float2 xv0 = unpack_bf16x2(A[(nt >> 1) * 4 + (nt & 1) * 2]);
                float2 xv1 = unpack_bf16x2(A[(nt >> 1) * 4 + (nt & 1) * 2 + 1]);
                float2 m2v = *(const float2*)(m2k + nt * 8 + 2 * qt);

                float z0 = ((da0 + db0) + (dc0 + dd0)) + (xv0.x - m2v.x);
                float z1 = ((da1 + db1) + (dc1 + dd1)) + (xv0.y - m2v.y);
                float z2 = ((da2 + db2) + (dc2 + dd2)) + (xv1.x - m2v.x);
                float z3 = ((da3 + db3) + (dc3 + dd3)) + (xv1.y - m2v.y);
                mh0 = fmaf(z0, z0, fmaf(z1, z1, mh0));
                mh1 = fmaf(z2, z2, fmaf(z3, z3, mh1));
            }
            mh0 += __shfl_xor_sync(0xffffffffu, mh0, 1);
            mh1 += __shfl_xor_sync(0xffffffffu, mh1, 1);
            mh0 += __shfl_xor_sync(0xffffffffu, mh0, 2);
            mh1 += __shfl_xor_sync(0xffffffffu, mh1, 2);

            float ck = sc[kk];
            float comp0 = fmaf(-0.5f, mh0, ck);
            float comp1 = fmaf(-0.5f, mh1, ck);
            float nm0 = fmaxf(mx0, comp0);
            s0 = s0 * __expf(mx0 - nm0) + __expf(comp0 - nm0);
            mx0 = nm0;
            float nm1 = fmaxf(mx1, comp1);
            s1 = s1 * __expf(mx1 - nm1) + __expf(comp1 - nm1);
            mx1 = nm1;
        }

        if (qt == 0) {
            int idx = chunk * B_SZ + mb + g;
            g_pm[idx] = mx0;
            g_ps[idx] = s0;
            g_pm[idx + 8] = mx1;
            g_ps[idx + 8] = s1;
        }
    }
}

// ---------------------------------------------------------------------------
__global__ void lse_reduce_kernel() {
    __shared__ float red[256];
    int t = threadIdx.x;
    int b = blockIdx.x * 256 + t;
    float m = g_pm[b];
    float s = g_ps[b];
#pragma unroll
    for (int c = 1; c < CHUNKS; ++c) {
        float mc = g_pm[c * B_SZ + b];
        float scv = g_ps[c * B_SZ + b];
        float nm = fmaxf(m, mc);
        s = s * __expf(m - nm) + scv * __expf(mc - nm);
        m = nm;
    }
    red[t] = m + __logf(s);
    __syncthreads();
    for (int s2 = 128; s2 > 0; s2 >>= 1) {
        if (t < s2) red[t] += red[t + s2];
        __syncthreads();
    }
    if (t == 0) g_partial[blockIdx.x] = red[0];
}

__global__ void final_kernel(float* __restrict__ out) {
    __shared__ float red[128];
    int t = threadIdx.x;
    red[t] = g_partial[t];
    __syncthreads();
    for (int s = 64; s > 0; s >>= 1) {
        if (t < s) red[t] += red[t + s];
        __syncthreads();
    }
    if (t == 0) out[0] = -red[0] / (float)B_SZ;
}

extern "C" void kernel_launch(void* const* d_in, const int* in_sizes, int n_in,
                              void* d_out, int out_size) {
    const float* x = 0;
    const float* means_raw = 0;
    const float* scale_raw = 0;
    const float* weights_raw = 0;
    for (int i = 0; i < n_in; ++i) {
        if (in_sizes[i] == B_SZ * D_SZ)        x = (const float*)d_in[i];
        if (in_sizes[i] == K_SZ * D_SZ)        means_raw = (const float*)d_in[i];
        if (in_sizes[i] == K_SZ * D_SZ * D_SZ) scale_raw = (const float*)d_in[i];
        if (in_sizes[i] == K_SZ)               weights_raw = (const float*)d_in[i];
    }

    cudaFuncSetAttribute(main_kernel,
                         cudaFuncAttributeMaxDynamicSharedMemorySize, SMEM_BYTES);

    logw_kernel<<<1, K_SZ>>>(weights_raw);
    prep_kernel<<<K_SZ, D_SZ>>>(means_raw, scale_raw);
    main_kernel<<<GRID_MAIN, THREADS_MAIN, SMEM_BYTES>>>(x);
    lse_reduce_kernel<<<128, 256>>>();
    final_kernel<<<1, 128>>>((float*)d_out);
}

// round 14
// speedup vs baseline: 1.1847x; 1.1847x over previous
#include <cuda_runtime.h>
#include <cuda_bf16.h>
#include <math.h>

#define B_SZ 32768
#define K_SZ 64
#define D_SZ 64

#define CHUNKS 8
#define KPC 8             // k per chunk
#define BPC 37            // blocks per chunk
#define GRID_MAIN 296     // CHUNKS * BPC; 2 blocks/SM, one wave at occ 2
#define THREADS_MAIN 256  // 8 warps x 16 samples
#define TILE_S 128
#define NTILES 256        // B_SZ / TILE_S

#define S_MEAN  (1.0f / 64.0f)
#define S_SCALE (1.0f / 512.0f)
#define S_W     (0.125f)
#define LOG_2PI 1.8378770664093453f
#define NEG_BIG (-3.0e38f)

// dynamic smem: E chunk 64KB | m2 2KB | c 32B  (+1KB align slack)
#define SM_M2   65536
#define SM_C    67584
#define SMEM_BYTES 69632

__device__ __nv_bfloat16 g_Eb[K_SZ * D_SZ * D_SZ];   // E = Linv - I (bf16)
__device__ float g_m2[K_SZ * D_SZ];
__device__ float g_c[K_SZ];
__device__ float g_logw[K_SZ];
__device__ float g_pm[CHUNKS * B_SZ];
__device__ float g_ps[CHUNKS * B_SZ];
__device__ float g_partial[128];

// ---------------- PTX helpers (braces in strings written as \173 \175) ----
__device__ __forceinline__ void cp16(unsigned dst, const void* src) {
    asm volatile("cp.async.cg.shared.global [%0], [%1], 16;"
                 :: "r"(dst), "l"(__cvta_generic_to_global(src)) : "memory");
}
__device__ __forceinline__ void cp_commit() {
    asm volatile("cp.async.commit_group;" ::: "memory");
}
__device__ __forceinline__ void cp_wait0() {
    asm volatile("cp.async.wait_group 0;" ::: "memory");
}
__device__ __forceinline__ void ldsm4(unsigned& r0, unsigned& r1,
                                      unsigned& r2, unsigned& r3, unsigned a) {
    asm volatile("ldmatrix.sync.aligned.m8n8.x4.shared.b16 \173%0,%1,%2,%3\175, [%4];"
                 : "=r"(r0), "=r"(r1), "=r"(r2), "=r"(r3) : "r"(a));
}
__device__ __forceinline__ void mma_bf16(float& c0, float& c1, float& c2, float& c3,
                                         unsigned a0, unsigned a1, unsigned a2, unsigned a3,
                                         unsigned b0, unsigned b1) {
    asm volatile("mma.sync.aligned.m16n8k16.row.col.f32.bf16.bf16.f32 "
                 "\173%0,%1,%2,%3\175, \173%4,%5,%6,%7\175, \173%8,%9\175, \173%0,%1,%2,%3\175;"
                 : "+f"(c0), "+f"(c1), "+f"(c2), "+f"(c3)
                 : "r"(a0), "r"(a1), "r"(a2), "r"(a3), "r"(b0), "r"(b1));
}
__device__ __forceinline__ unsigned pack_bf16x2(float lo, float hi) {
    __nv_bfloat162 h = __floats2bfloat162_rn(lo, hi);
    return *reinterpret_cast<unsigned*>(&h);
}
__device__ __forceinline__ float2 unpack_bf16x2(unsigned u) {
    __nv_bfloat162 h = *reinterpret_cast<__nv_bfloat162*>(&u);
    return __bfloat1622float2(h);
}

// ---------------------------------------------------------------------------
__global__ void logw_kernel(const float* __restrict__ wraw) {
    __shared__ float red[K_SZ];
    int t = threadIdx.x;
    float v = wraw[t] * S_W;
    red[t] = v;
    __syncthreads();
    for (int s = 32; s > 0; s >>= 1) {
        if (t < s) red[t] = fmaxf(red[t], red[t + s]);
        __syncthreads();
    }
    float m = red[0];
    __syncthreads();
    red[t] = __expf(v - m);
    __syncthreads();
    for (int s = 32; s > 0; s >>= 1) {
        if (t < s) red[t] += red[t + s];
        __syncthreads();
    }
    float lse = m + __logf(red[0]);
    g_logw[t] = v - lse;
}

__global__ void prep_kernel(const float* __restrict__ means_raw,
                            const float* __restrict__ scale_raw) {
    __shared__ float sL [D_SZ * D_SZ];
    __shared__ float sLI[D_SZ * D_SZ];
    __shared__ float red[D_SZ];
    int k = blockIdx.x;
    int t = threadIdx.x;
    const float* src = scale_raw + (size_t)k * D_SZ * D_SZ;

    for (int idx = t; idx < D_SZ * D_SZ; idx += D_SZ) {
        int i = idx >> 6;
        int j = idx & 63;
        float v = src[idx] * S_SCALE;
        float dv = expf(v);
        float off = (j < i) ? v : 0.0f;
        sL[idx] = (j == i) ? dv : off;
    }
    red[t] = src[t * D_SZ + t] * S_SCALE;
    __syncthreads();
    for (int s = 32; s > 0; s >>= 1) {
        if (t < s) red[t] += red[t + s];
        __syncthreads();
    }
    float hld = red[0];

    int j = t;
    for (int i = 0; i < j; ++i) sLI[i * D_SZ + j] = 0.0f;
    sLI[j * D_SZ + j] = 1.0f / sL[j * D_SZ + j];
    for (int i = j + 1; i < D_SZ; ++i) {
        float s = 0.0f;
        for (int m = j; m < i; ++m)
            s += sL[i * D_SZ + m] * sLI[m * D_SZ + j];
        sLI[i * D_SZ + j] = -s / sL[i * D_SZ + i];
    }
    __syncthreads();

    float mm = 0.0f;
    for (int jj = 0; jj <= t; ++jj)
        mm += sLI[t * D_SZ + jj] * (means_raw[k * D_SZ + jj] * S_MEAN);
    g_m2[k * D_SZ + t] = mm;

    if (t == 0)
        g_c[k] = -0.5f * (float)D_SZ * LOG_2PI - hld + g_logw[k];

    // E = Linv - I (bf16): systematic rounding scales with |E|, unit diagonal
    // re-added exactly in fp32 downstream
    for (int idx = t; idx < D_SZ * D_SZ; idx += D_SZ) {
        int i = idx >> 6;
        int jj2 = idx & 63;
        float v = sLI[idx] - ((i == jj2) ? 1.0f : 0.0f);
        g_Eb[(size_t)k * 4096 + idx] = __float2bfloat16(v);
    }
}

// ---------------------------------------------------------------------------
// Main: split-k persistent, 2 blocks/SM. Block = one k-chunk (8 k), E chunk
// resident in smem for the whole kernel. z = x + E*x - m2 (identity in fp32
// from A-frags). 2 depth-2 MMA chains per nt (R12 shape).
// ---------------------------------------------------------------------------
extern __shared__ __align__(16) char dsm[];

__global__ void __launch_bounds__(THREADS_MAIN, 2)
main_kernel(const float* __restrict__ x) {
    const int tid  = threadIdx.x;
    const int warp = tid >> 5;
    const int lane = tid & 31;
    const int g    = lane >> 2;
    const int qt   = lane & 3;

    unsigned raw = (unsigned)__cvta_generic_to_shared(dsm);
    unsigned ab = (raw + 1023u) & ~1023u;
    char* abp = dsm + (ab - raw);

    const unsigned wa  = ab;
    const unsigned m2a = ab + SM_M2;
    const unsigned ca  = ab + SM_C;
    const float* sm2 = (const float*)(abp + SM_M2);
    const float* sc  = (const float*)(abp + SM_C);

    const int chunk = blockIdx.x & 7;
    const int jb    = blockIdx.x >> 3;     // 0..36
    const int k0    = chunk * KPC;

    // ---- stage E chunk (8k x 8KB, swizzled) + m2 + c, once ----
    for (int c = tid; c < KPC * 512; c += THREADS_MAIN) {
        int k   = c >> 9;
        int rem = c & 511;
        int row = rem >> 3;
        int cc  = rem & 7;
        unsigned dst = wa + (unsigned)(k * 8192 + row * 128 + ((cc ^ (row & 7)) * 16));
        cp16(dst, g_Eb + (size_t)(k0 + k) * 4096 + row * 64 + cc * 8);
    }
    {
        int c = tid;
        if (c < 128) cp16(m2a + (unsigned)(c * 16), g_m2 + k0 * 64 + c * 4);
        if (c < 2)   cp16(ca + (unsigned)(c * 16), g_c + k0 + c * 4);
    }
    cp_commit();
    cp_wait0();
    __syncthreads();

    const unsigned rbase = (unsigned)((lane & 7) * 128);
    const unsigned c0off = (unsigned)((((lane >> 3)) ^ (lane & 7)) * 16);
    const unsigned c1off = (unsigned)((((lane >> 3) + 4) ^ (lane & 7)) * 16);

    for (int t = jb; t < NTILES; t += BPC) {
        const int mb = t * TILE_S + warp * 16;
        const float* xr0 = x + (size_t)(mb + g) * D_SZ;
        const float* xr1 = x + (size_t)(mb + g + 8) * D_SZ;

        unsigned A[16];
#pragma unroll
        for (int jt = 0; jt < 4; ++jt) {
#pragma unroll
            for (int part = 0; part < 4; ++part) {
                const float* rp = (part & 1) ? xr1 : xr0;
                int jj = jt * 16 + 2 * qt + ((part & 2) ? 8 : 0);
                float2 v = *(const float2*)(rp + jj);
                A[jt * 4 + part] = pack_bf16x2(v.x, v.y);
            }
        }

        float mx0 = NEG_BIG, s0 = 0.0f;
        float mx1 = NEG_BIG, s1 = 0.0f;

        for (int kk = 0; kk < KPC; ++kk) {
            const unsigned wk = wa + (unsigned)(kk * 8192) + rbase;
            const float* m2k = sm2 + kk * 64;

            float mh0 = 0.0f, mh1 = 0.0f;
#pragma unroll
            for (int nt = 0; nt < 8; ++nt) {
                unsigned base = wk + (unsigned)(nt * 1024);
                unsigned bh0, bh1, bh2, bh3, bg0, bg1, bg2, bg3;
                ldsm4(bh0, bh1, bh2, bh3, base + c0off);
                ldsm4(bg0, bg1, bg2, bg3, base + c1off);

                float da0 = 0.0f, da1 = 0.0f, da2 = 0.0f, da3 = 0.0f;
                float db0 = 0.0f, db1 = 0.0f, db2 = 0.0f, db3 = 0.0f;
                mma_bf16(da0, da1, da2, da3, A[0],  A[1],  A[2],  A[3],  bh0, bh1);
                mma_bf16(db0, db1, db2, db3, A[8],  A[9],  A[10], A[11], bg0, bg1);
                mma_bf16(da0, da1, da2, da3, A[4],  A[5],  A[6],  A[7],  bh2, bh3);
                mma_bf16(db0, db1, db2, db3, A[12], A[13], A[14], A[15], bg2, bg3);

                // identity term: x values for output cols nt*8+2qt(+1)
                float2 xv0 = unpack_bf16x2(A[(nt >> 1) * 4 + (nt & 1) * 2]);
                float2 xv1 = unpack_bf16x2(A[(nt >> 1) * 4 + (nt & 1) * 2 + 1]);
                float2 m2v = *(const float2*)(m2k + nt * 8 + 2 * qt);

                float z0 = (da0 + db0) + (xv0.x - m2v.x);
                float z1 = (da1 + db1) + (xv0.y - m2v.y);
                float z2 = (da2 + db2) + (xv1.x - m2v.x);
                float z3 = (da3 + db3) + (xv1.y - m2v.y);
                mh0 = fmaf(z0, z0, fmaf(z1, z1, mh0));
                mh1 = fmaf(z2, z2, fmaf(z3, z3, mh1));
            }
            mh0 += __shfl_xor_sync(0xffffffffu, mh0, 1);
            mh1 += __shfl_xor_sync(0xffffffffu, mh1, 1);
            mh0 += __shfl_xor_sync(0xffffffffu, mh0, 2);
            mh1 += __shfl_xor_sync(0xffffffffu, mh1, 2);

            float ck = sc[kk];
            float comp0 = fmaf(-0.5f, mh0, ck);
            float comp1 = fmaf(-0.5f, mh1, ck);
            float nm0 = fmaxf(mx0, comp0);
            s0 = s0 * __expf(mx0 - nm0) + __expf(comp0 - nm0);
            mx0 = nm0;
            float nm1 = fmaxf(mx1, comp1);
            s1 = s1 * __expf(mx1 - nm1) + __expf(comp1 - nm1);
            mx1 = nm1;
        }

        if (qt == 0) {
            int idx = chunk * B_SZ + mb + g;
            g_pm[idx] = mx0;
            g_ps[idx] = s0;
            g_pm[idx + 8] = mx1;
            g_ps[idx + 8] = s1;
        }
    }
}

// ---------------------------------------------------------------------------
__global__ void lse_reduce_kernel() {
    __shared__ float red[256];
    int t = threadIdx.x;
    int b = blockIdx.x * 256 + t;
    float m = g_pm[b];
    float s = g_ps[b];
#pragma unroll
    for (int c = 1; c < CHUNKS; ++c) {
        float mc = g_pm[c * B_SZ + b];
        float scv = g_ps[c * B_SZ + b];
        float nm = fmaxf(m, mc);
        s = s * __expf(m - nm) + scv * __expf(mc - nm);
        m = nm;
    }
    red[t] = m + __logf(s);
    __syncthreads();
    for (int s2 = 128; s2 > 0; s2 >>= 1) {
        if (t < s2) red[t] += red[t + s2];
        __syncthreads();
    }
    if (t == 0) g_partial[blockIdx.x] = red[0];
}

__global__ void final_kernel(float* __restrict__ out) {
    __shared__ float red[128];
    int t = threadIdx.x;
    red[t] = g_partial[t];
    __syncthreads();
    for (int s = 64; s > 0; s >>= 1) {
        if (t < s) red[t] += red[t + s];
        __syncthreads();
    }
    if (t == 0) out[0] = -red[0] / (float)B_SZ;
}

extern "C" void kernel_launch(void* const* d_in, const int* in_sizes, int n_in,
                              void* d_out, int out_size) {
    const float* x = 0;
    const float* means_raw = 0;
    const float* scale_raw = 0;
    const float* weights_raw = 0;
    for (int i = 0; i < n_in; ++i) {
        if (in_sizes[i] == B_SZ * D_SZ)        x = (const float*)d_in[i];
        if (in_sizes[i] == K_SZ * D_SZ)        means_raw = (const float*)d_in[i];
        if (in_sizes[i] == K_SZ * D_SZ * D_SZ) scale_raw = (const float*)d_in[i];
        if (in_sizes[i] == K_SZ)               weights_raw = (const float*)d_in[i];
    }

    cudaFuncSetAttribute(main_kernel,
                         cudaFuncAttributeMaxDynamicSharedMemorySize, SMEM_BYTES);

    logw_kernel<<<1, K_SZ>>>(weights_raw);
    prep_kernel<<<K_SZ, D_SZ>>>(means_raw, scale_raw);
    main_kernel<<<GRID_MAIN, THREADS_MAIN, SMEM_BYTES>>>(x);
    lse_reduce_kernel<<<128, 256>>>();
    final_kernel<<<1, 128>>>((float*)d_out);
}